// round 17
// baseline (speedup 1.0000x reference)
#include <cuda_runtime.h>
#include <cuda_bf16.h>
#include <cstdint>

#define NN 100000
#define EE 640000
#define GG 64
#define SCAN_BLK 512
#define NBLK ((NN + SCAN_BLK - 1) / SCAN_BLK)   // 196

// ---------------- scratch ---------------------------------------------------
__device__ __align__(16) int   g_degi[NN];
__device__ __align__(16) int   g_cnt[NN];
__device__ __align__(16) int   g_incl[NN];
__device__ __align__(16) int   g_bsum[NBLK];
__device__ __align__(16) int   g_rowptr[NN + 1];
__device__ __align__(16) int   g_cursor[NN];
__device__ __align__(16) int   g_csr_src[EE];
__device__ __align__(16) float g_csr_w[EE];
__device__ __align__(16) float g_Y0[NN * 64];
__device__ __align__(16) float g_Y1[NN * 64];
__device__ __align__(16) float g_Y2[NN * 64];
__device__ __align__(16) float g_Z[NN * 64];
__device__ __align__(16) float g_H1[NN * 64];
__device__ __align__(16) float g_H2[NN * 32];
__device__ __align__(16) float g_H3[NN * 16];
__device__ __align__(16) __nv_bfloat16 g_Bfh[24576];  // weight frags (hi)
__device__ __align__(16) __nv_bfloat16 g_Bfl[24576];  // weight frags (lo)
__device__ __align__(16) float g_sc[64];
__device__ __align__(16) float g_sh[64];
__device__ __align__(16) float g_pool[GG * 16 + GG];

// ---------------- CSR build -------------------------------------------------
__global__ void k_degcnt(const int* __restrict__ ei) {
    int e = blockIdx.x * blockDim.x + threadIdx.x;
    if (e >= EE) return;
    int s = ei[e], d = ei[EE + e];
    if (s != d) {
        atomicAdd(&g_degi[s], 1);
        atomicAdd(&g_cnt[d], 1);
    }
}

__global__ void k_scan1() {
    __shared__ int sh[SCAN_BLK];
    int i = blockIdx.x * SCAN_BLK + threadIdx.x;
    int v = (i < NN) ? g_cnt[i] : 0;
    sh[threadIdx.x] = v;
    __syncthreads();
#pragma unroll
    for (int off = 1; off < SCAN_BLK; off <<= 1) {
        int t = (threadIdx.x >= off) ? sh[threadIdx.x - off] : 0;
        __syncthreads();
        sh[threadIdx.x] += t;
        __syncthreads();
    }
    if (i < NN) g_incl[i] = sh[threadIdx.x];
    if (threadIdx.x == SCAN_BLK - 1) g_bsum[blockIdx.x] = sh[threadIdx.x];
}

__global__ void k_scan2() {
    __shared__ int sh[256];
    int t = threadIdx.x;
    int v = (t < NBLK) ? g_bsum[t] : 0;
    sh[t] = v;
    __syncthreads();
#pragma unroll
    for (int off = 1; off < 256; off <<= 1) {
        int u = (t >= off) ? sh[t - off] : 0;
        __syncthreads();
        sh[t] += u;
        __syncthreads();
    }
    if (t < NBLK) g_bsum[t] = (t > 0) ? sh[t - 1] : 0;   // exclusive
}

__global__ void k_scan3() {
    int i = blockIdx.x * blockDim.x + threadIdx.x;
    if (i < NN) g_rowptr[i + 1] = g_incl[i] + g_bsum[i / SCAN_BLK];
    if (i == 0) g_rowptr[0] = 0;
}

__global__ void k_fill(const int* __restrict__ ei) {
    int e = blockIdx.x * blockDim.x + threadIdx.x;
    if (e >= EE) return;
    int s = ei[e], d = ei[EE + e];
    if (s == d) return;
    float is = rsqrtf((float)g_degi[s]);
    int dd = g_degi[d];
    float id = dd > 0 ? rsqrtf((float)dd) : 0.0f;
    float w = -is * id;
    int pos = atomicAdd(&g_cursor[d], 1);
    g_csr_src[pos] = s;
    g_csr_w[pos] = w;
}

// ---------------- BN-scale prep ---------------------------------------------
__global__ void k_prepS(const float* __restrict__ b, const float* __restrict__ g,
                        const float* __restrict__ be, const float* __restrict__ m,
                        const float* __restrict__ v, int Fout) {
    int tid = threadIdx.x;
    if (tid < Fout) {
        float s = g[tid] * rsqrtf(v[tid] + 1e-5f);
        g_sc[tid] = s;
        g_sh[tid] = (b[tid] - m[tid]) * s + be[tid];
    }
}

// ---- weight prep: fold Cheb coeffs, split bf16 hi/lo, pack as mma B-frags --
// B logical layout [k][n] (K x N3).  m16n8k16 col-major B fragment:
//   lane = nin*4 + ((kin&7)>>1), reg = kin>>3, half = kin&1
__global__ void k_prepB(const float* __restrict__ W, int Fin, int Fout, int NT) {
    int i = blockIdx.x * blockDim.x + threadIdx.x;
    int N3 = 3 * Fout;
    if (i >= N3 * Fin) return;
    int n = i / Fin, k = i % Fin;
    int tot = Fin * Fout;
    float val;
    if (n < Fout)          val = W[k * Fout + n] - W[2 * tot + k * Fout + n];
    else if (n < 2 * Fout) val = W[tot + k * Fout + (n - Fout)];
    else                   val = 2.0f * W[2 * tot + k * Fout + (n - 2 * Fout)];
    __nv_bfloat16 h = __float2bfloat16(val);
    __nv_bfloat16 l = __float2bfloat16(val - __bfloat162float(h));
    int t = k >> 4, j = n >> 3, kin = k & 15, nin = n & 7;
    int lane = (nin << 2) | ((kin & 7) >> 1);
    int reg = kin >> 3, half = kin & 1;
    int idx = (((t * NT + j) * 32 + lane) * 2 + reg) * 2 + half;
    g_Bfh[idx] = h;
    g_Bfl[idx] = l;
}

// -------- mma.sync GEMM: [Y0|Y1|Y2] = A @ Wc  (split bf16, fp32 accum) -----
template <int FIN, int FOUT>
__global__ void __launch_bounds__(256) k_mma(const float* __restrict__ A,
                                             float* __restrict__ Y0,
                                             float* __restrict__ Y1,
                                             float* __restrict__ Y2) {
    constexpr int N3 = 3 * FOUT;
    constexpr int KT = FIN / 16;
    constexpr int NT = N3 / 8;
    constexpr int ASTR = FIN + 4;            // bf16 units, padded
    constexpr int ASZ = 128 * ASTR * 2;      // bytes
    constexpr int BSZ = KT * NT * 256;       // bytes
    constexpr int OSTR = N3 + 4;             // fp32 units, padded
    constexpr int C4 = FIN / 4;
    constexpr int F4 = N3 / 4;
    extern __shared__ __align__(16) uint8_t smem[];
    __nv_bfloat16* Ah = (__nv_bfloat16*)(smem);
    __nv_bfloat16* Al = (__nv_bfloat16*)(smem + ASZ);
    uint32_t* Bh = (uint32_t*)(smem + 2 * ASZ);
    uint32_t* Bl = (uint32_t*)(smem + 2 * ASZ + BSZ);
    int tid = threadIdx.x, wid = tid >> 5, lane = tid & 31;
    int m0 = blockIdx.x * 128;

    // copy pre-packed B fragments to smem
    for (int idx = tid; idx < BSZ / 16; idx += 256) {
        ((uint4*)Bh)[idx] = ((const uint4*)g_Bfh)[idx];
        ((uint4*)Bl)[idx] = ((const uint4*)g_Bfl)[idx];
    }
    // load A tile, split fp32 -> bf16 hi/lo
    for (int idx = tid; idx < 128 * C4; idx += 256) {
        int r = idx / C4, c4 = (idx % C4) * 4;
        int row = m0 + r;
        float4 v = make_float4(0.f, 0.f, 0.f, 0.f);
        if (row < NN) v = *(const float4*)(A + (size_t)row * FIN + c4);
        __nv_bfloat16 h0 = __float2bfloat16(v.x), h1 = __float2bfloat16(v.y);
        __nv_bfloat16 h2 = __float2bfloat16(v.z), h3 = __float2bfloat16(v.w);
        __nv_bfloat16 l0 = __float2bfloat16(v.x - __bfloat162float(h0));
        __nv_bfloat16 l1 = __float2bfloat16(v.y - __bfloat162float(h1));
        __nv_bfloat16 l2 = __float2bfloat16(v.z - __bfloat162float(h2));
        __nv_bfloat16 l3 = __float2bfloat16(v.w - __bfloat162float(h3));
        *(__nv_bfloat162*)(Ah + r * ASTR + c4)     = __halves2bfloat162(h0, h1);
        *(__nv_bfloat162*)(Ah + r * ASTR + c4 + 2) = __halves2bfloat162(h2, h3);
        *(__nv_bfloat162*)(Al + r * ASTR + c4)     = __halves2bfloat162(l0, l1);
        *(__nv_bfloat162*)(Al + r * ASTR + c4 + 2) = __halves2bfloat162(l2, l3);
    }
    __syncthreads();

    int g = lane >> 2, tq = lane & 3;
    int r0 = wid * 16 + g;
    float acc[NT][4];
#pragma unroll
    for (int j = 0; j < NT; j++)
#pragma unroll
        for (int q = 0; q < 4; q++) acc[j][q] = 0.0f;

    // D = Ah*Bh + Al*Bh + Ah*Bl
#pragma unroll 1
    for (int pass = 0; pass < 3; pass++) {
        const __nv_bfloat16* ash = (pass == 1) ? Al : Ah;
        const uint32_t* bsh = (pass == 2) ? Bl : Bh;
#pragma unroll 1
        for (int t = 0; t < KT; t++) {
            int kb = t * 16 + 2 * tq;
            uint32_t a0 = *(const uint32_t*)(ash + r0 * ASTR + kb);
            uint32_t a1 = *(const uint32_t*)(ash + (r0 + 8) * ASTR + kb);
            uint32_t a2 = *(const uint32_t*)(ash + r0 * ASTR + kb + 8);
            uint32_t a3 = *(const uint32_t*)(ash + (r0 + 8) * ASTR + kb + 8);
            const uint32_t* bp = bsh + t * NT * 64 + lane * 2;
#pragma unroll
            for (int j = 0; j < NT; j++) {
                uint2 bb = *(const uint2*)bp;
                bp += 64;
                asm volatile(
                    "mma.sync.aligned.m16n8k16.row.col.f32.bf16.bf16.f32 "
                    "{%0,%1,%2,%3},{%4,%5,%6,%7},{%8,%9},{%0,%1,%2,%3};"
                    : "+f"(acc[j][0]), "+f"(acc[j][1]),
                      "+f"(acc[j][2]), "+f"(acc[j][3])
                    : "r"(a0), "r"(a1), "r"(a2), "r"(a3),
                      "r"(bb.x), "r"(bb.y));
            }
        }
    }

    // epilogue: stage in smem (reuse), then coalesced float4 stores
    __syncthreads();
    float* so = (float*)smem;
#pragma unroll
    for (int j = 0; j < NT; j++) {
        int n0 = 8 * j + 2 * tq;
        *(float2*)&so[(wid * 16 + g) * OSTR + n0] =
            make_float2(acc[j][0], acc[j][1]);
        *(float2*)&so[(wid * 16 + g + 8) * OSTR + n0] =
            make_float2(acc[j][2], acc[j][3]);
    }
    __syncthreads();
    for (int idx = tid; idx < 128 * F4; idx += 256) {
        int r = idx / F4, gc = (idx % F4) * 4;
        int node = m0 + r;
        if (node >= NN) continue;
        float4 v = *(float4*)&so[r * OSTR + gc];
        float* dst;
        if (gc < FOUT)          dst = Y0 + (size_t)node * FOUT + gc;
        else if (gc < 2 * FOUT) dst = Y1 + (size_t)node * FOUT + gc - FOUT;
        else                    dst = Y2 + (size_t)node * FOUT + gc - 2 * FOUT;
        *(float4*)dst = v;
    }
}

// ------- unified gather: O[i] = B[i] + P(S)[i]   (+BN+leaky if EPI) --------
template <int F, int TPN, bool EPI>
__global__ void __launch_bounds__(256) k_gath(const float* __restrict__ S,
                                              const float* __restrict__ B,
                                              float* __restrict__ O) {
    constexpr int V = F / TPN;
    int gid = blockIdx.x * blockDim.x + threadIdx.x;
    int node = gid / TPN;
    if (node >= NN) return;
    int col = (gid % TPN) * V;
    int r0 = g_rowptr[node], r1 = g_rowptr[node + 1];
    float acc[V];
#pragma unroll
    for (int v = 0; v < V; v++) acc[v] = 0.0f;

    const float* Sc = S + col;
    int j = r0;
    for (; j + 1 < r1; j += 2) {
        int   s0 = __ldg(g_csr_src + j), s1 = __ldg(g_csr_src + j + 1);
        float w0 = __ldg(g_csr_w + j),   w1 = __ldg(g_csr_w + j + 1);
        const float* p0 = Sc + (size_t)s0 * F;
        const float* p1 = Sc + (size_t)s1 * F;
        if constexpr (V == 2) {
            float2 a = *(const float2*)p0, b = *(const float2*)p1;
            acc[0] += w0 * a.x + w1 * b.x;
            acc[1] += w0 * a.y + w1 * b.y;
        } else {
            acc[0] += w0 * p0[0] + w1 * p1[0];
        }
    }
    if (j < r1) {
        int   s0 = __ldg(g_csr_src + j);
        float w0 = __ldg(g_csr_w + j);
        const float* p0 = Sc + (size_t)s0 * F;
        if constexpr (V == 2) {
            float2 a = *(const float2*)p0;
            acc[0] += w0 * a.x; acc[1] += w0 * a.y;
        } else {
            acc[0] += w0 * p0[0];
        }
    }

#pragma unroll
    for (int v = 0; v < V; v++) {
        float y = B[(size_t)node * F + col + v] + acc[v];
        if constexpr (EPI) {
            y = y * g_sc[col + v] + g_sh[col + v];
            y = y > 0.0f ? y : 0.01f * y;
        }
        O[(size_t)node * F + col + v] = y;
    }
}

// ---------------- global mean pool ------------------------------------------
__global__ void k_pool(const float* __restrict__ H, const int* __restrict__ batch) {
    constexpr int CH = 16;
    int tid = blockIdx.x * blockDim.x + threadIdx.x;
    int n0 = tid * CH;
    if (n0 >= NN) return;
    int n1 = n0 + CH; if (n1 > NN) n1 = NN;

    float acc[16];
#pragma unroll
    for (int f = 0; f < 16; f++) acc[f] = 0.0f;
    float cnt = 0.0f;
    int cur = batch[n0];

    for (int n = n0; n < n1; n++) {
        int b = batch[n];
        if (b != cur) {
#pragma unroll
            for (int f = 0; f < 16; f++) atomicAdd(&g_pool[cur * 16 + f], acc[f]);
            atomicAdd(&g_pool[GG * 16 + cur], cnt);
#pragma unroll
            for (int f = 0; f < 16; f++) acc[f] = 0.0f;
            cnt = 0.0f;
            cur = b;
        }
        const float4* r = (const float4*)(H + (size_t)n * 16);
        float4 r0 = r[0], r1 = r[1], r2 = r[2], r3 = r[3];
        acc[0] += r0.x; acc[1] += r0.y; acc[2] += r0.z; acc[3] += r0.w;
        acc[4] += r1.x; acc[5] += r1.y; acc[6] += r1.z; acc[7] += r1.w;
        acc[8] += r2.x; acc[9] += r2.y; acc[10] += r2.z; acc[11] += r2.w;
        acc[12] += r3.x; acc[13] += r3.y; acc[14] += r3.z; acc[15] += r3.w;
        cnt += 1.0f;
    }
#pragma unroll
    for (int f = 0; f < 16; f++) atomicAdd(&g_pool[cur * 16 + f], acc[f]);
    atomicAdd(&g_pool[GG * 16 + cur], cnt);
}

// ---------------- final linear ----------------------------------------------
__global__ void k_final(const float* __restrict__ lw, const float* __restrict__ lb,
                        float* __restrict__ out) {
    int tid = threadIdx.x;
    if (tid >= GG * 2) return;
    int g = tid >> 1, o = tid & 1;
    float c = g_pool[GG * 16 + g];
    if (c < 1.0f) c = 1.0f;
    float inv = 1.0f / c;
    float s = 0.0f;
#pragma unroll
    for (int f = 0; f < 16; f++)
        s += g_pool[g * 16 + f] * inv * lw[o * 16 + f];
    out[tid] = s + lb[o];
}

// ---------------- host orchestration ---------------------------------------
extern "C" void kernel_launch(void* const* d_in, const int* in_sizes, int n_in,
                              void* d_out, int out_size) {
    (void)in_sizes; (void)n_in; (void)out_size;
    const float* x     = (const float*)d_in[0];
    const int*   ei    = (const int*)d_in[1];
    const int*   batch = (const int*)d_in[2];
    const float* W1 = (const float*)d_in[3],  *b1 = (const float*)d_in[4];
    const float* g1 = (const float*)d_in[5],  *be1 = (const float*)d_in[6];
    const float* m1 = (const float*)d_in[7],  *v1 = (const float*)d_in[8];
    const float* W2 = (const float*)d_in[9],  *b2 = (const float*)d_in[10];
    const float* g2 = (const float*)d_in[11], *be2 = (const float*)d_in[12];
    const float* m2 = (const float*)d_in[13], *v2 = (const float*)d_in[14];
    const float* W3 = (const float*)d_in[15], *b3 = (const float*)d_in[16];
    const float* g3 = (const float*)d_in[17], *be3 = (const float*)d_in[18];
    const float* m3 = (const float*)d_in[19], *v3 = (const float*)d_in[20];
    const float* lw = (const float*)d_in[21], *lb = (const float*)d_in[22];
    float* out = (float*)d_out;

    float *p_Y0, *p_Y1, *p_Y2, *p_Z, *p_H1, *p_H2, *p_H3, *p_pool;
    int *p_degi, *p_cnt, *p_rowptr, *p_cursor;
    cudaGetSymbolAddress((void**)&p_degi,   g_degi);
    cudaGetSymbolAddress((void**)&p_cnt,    g_cnt);
    cudaGetSymbolAddress((void**)&p_rowptr, g_rowptr);
    cudaGetSymbolAddress((void**)&p_cursor, g_cursor);
    cudaGetSymbolAddress((void**)&p_Y0,     g_Y0);
    cudaGetSymbolAddress((void**)&p_Y1,     g_Y1);
    cudaGetSymbolAddress((void**)&p_Y2,     g_Y2);
    cudaGetSymbolAddress((void**)&p_Z,      g_Z);
    cudaGetSymbolAddress((void**)&p_H1,     g_H1);
    cudaGetSymbolAddress((void**)&p_H2,     g_H2);
    cudaGetSymbolAddress((void**)&p_H3,     g_H3);
    cudaGetSymbolAddress((void**)&p_pool,   g_pool);

    cudaMemsetAsync(p_degi, 0, NN * sizeof(int));
    cudaMemsetAsync(p_cnt,  0, NN * sizeof(int));
    cudaMemsetAsync(p_pool, 0, (GG * 16 + GG) * sizeof(float));

    int eb = (EE + 255) / 256;

    // ----- CSR build -----
    k_degcnt<<<eb, 256>>>(ei);
    k_scan1<<<NBLK, SCAN_BLK>>>();
    k_scan2<<<1, 256>>>();
    k_scan3<<<(NN + 255) / 256, 256>>>();
    cudaMemcpyAsync(p_cursor, p_rowptr, NN * sizeof(int), cudaMemcpyDeviceToDevice);
    k_fill<<<eb, 256>>>(ei);

    int gmm = (NN + 127) / 128;              // 782 CTAs
    int gw32 = ((NN * 32) + 255) / 256;
    int gw16 = ((NN * 16) + 255) / 256;

    // dyn smem: max(2*ASZ + 2*BSZ, 128*OSTR*4)
    const int SZ1 = 165888;   // 2*33792 + 2*49152  (stage 100352)
    const int SZ2 = 59392;    // 2*17408 + 2*12288  (stage 51200)
    const int SZ3 = 26624;    // stage dominates (2*9216+2*3072 = 24576)
    cudaFuncSetAttribute(k_mma<128, 64>,
                         cudaFuncAttributeMaxDynamicSharedMemorySize, SZ1);
    cudaFuncSetAttribute(k_mma<64, 32>,
                         cudaFuncAttributeMaxDynamicSharedMemorySize, SZ2);
    cudaFuncSetAttribute(k_mma<32, 16>,
                         cudaFuncAttributeMaxDynamicSharedMemorySize, SZ3);

    // ----- layer 1: 128 -> 64 -----
    k_prepS<<<1, 64>>>(b1, g1, be1, m1, v1, 64);
    k_prepB<<<(192 * 128 + 255) / 256, 256>>>(W1, 128, 64, 24);
    k_mma<128, 64><<<gmm, 256, SZ1>>>(x, p_Y0, p_Y1, p_Y2);
    k_gath<64, 32, false><<<gw32, 256>>>(p_Y2, p_Y1, p_Z);
    k_gath<64, 32, true ><<<gw32, 256>>>(p_Z,  p_Y0, p_H1);

    // ----- layer 2: 64 -> 32 -----
    k_prepS<<<1, 64>>>(b2, g2, be2, m2, v2, 32);
    k_prepB<<<(96 * 64 + 255) / 256, 256>>>(W2, 64, 32, 12);
    k_mma<64, 32><<<gmm, 256, SZ2>>>(p_H1, p_Y0, p_Y1, p_Y2);
    k_gath<32, 32, false><<<gw32, 256>>>(p_Y2, p_Y1, p_Z);
    k_gath<32, 32, true ><<<gw32, 256>>>(p_Z,  p_Y0, p_H2);

    // ----- layer 3: 32 -> 16 -----
    k_prepS<<<1, 64>>>(b3, g3, be3, m3, v3, 16);
    k_prepB<<<(48 * 32 + 255) / 256, 256>>>(W3, 32, 16, 6);
    k_mma<32, 16><<<gmm, 256, SZ3>>>(p_H2, p_Y0, p_Y1, p_Y2);
    k_gath<16, 16, false><<<gw16, 256>>>(p_Y2, p_Y1, p_Z);
    k_gath<16, 16, true ><<<gw16, 256>>>(p_Z,  p_Y0, p_H3);

    // ----- pool + classifier -----
    {
        int threads = (NN + 15) / 16;
        int gb = (threads + 255) / 256;
        k_pool<<<gb, 256>>>(p_H3, batch);
    }
    k_final<<<1, 128>>>(lw, lb, out);
}